// round 3
// baseline (speedup 1.0000x reference)
#include <cuda_runtime.h>
#include <cuda_bf16.h>

// Problem constants (fixed shapes from setup_inputs)
#define BB 8
#define KK 8
#define HH 1024
#define WW 1024
#define CH 16            // rows per thread chunk
#define GAMMA_C 10.0f
#define EPS_SQRT_C 1e-24f

// Scratch accumulators: [0..63] = nom[b*K+k], [64..127] = denom[b*K+k]
__device__ float g_acc[2 * BB * KK];

__global__ void zero_acc_kernel() {
    g_acc[threadIdx.x] = 0.0f;
}

__global__ __launch_bounds__(256) void clustering_main_kernel(
    const float* __restrict__ img,      // (B,1,H,W)
    const float* __restrict__ spacing,  // (2,)
    const float* __restrict__ p)        // (B,K,H,W)
{
    const int b  = blockIdx.z;
    const int h0 = blockIdx.y * CH;
    const int w0 = 4 * threadIdx.x;     // blockDim.x = 256 covers W=1024 via float4

    const float sx = spacing[0];
    const float sy = spacing[1];
    const float smin   = fminf(sx, sy);
    const float inv_sx = 1.0f / sx;
    const float inv_sy = 1.0f / sy;

    const float* Ib = img + (size_t)b * HH * WW;
    const float* pb = p   + (size_t)b * KK * HH * WW;

    float nom[KK], den[KK];
#pragma unroll
    for (int k = 0; k < KK; k++) { nom[k] = 0.0f; den[k] = 0.0f; }

    const bool has_right = (w0 + 4 < WW);

    // Prime current row (h0)
    float4 iC = *(const float4*)(Ib + (size_t)h0 * WW + w0);
    float  iCR = has_right ? Ib[(size_t)h0 * WW + w0 + 4] : iC.w;
    float4 pC[KK];
    float  pCR[KK];
#pragma unroll
    for (int k = 0; k < KK; k++) {
        const float* pk = pb + (size_t)k * HH * WW;
        pC[k]  = *(const float4*)(pk + (size_t)h0 * WW + w0);
        pCR[k] = has_right ? pk[(size_t)h0 * WW + w0 + 4] : pC[k].w;
    }

    for (int r = 0; r < CH; r++) {
        const int h  = h0 + r;
        const int hp = (h + 1 < HH) ? (h + 1) : (HH - 1);

        // Next row of I
        float4 iN  = *(const float4*)(Ib + (size_t)hp * WW + w0);
        float  iNR = has_right ? Ib[(size_t)hp * WW + w0 + 4] : iN.w;

        // Edge weight per lane (reused across all K channels)
        float wE[4];
        {
            const float ix[4] = { iN.x - iC.x, iN.y - iC.y, iN.z - iC.z, iN.w - iC.w };
            const float iy[4] = { iC.y - iC.x, iC.z - iC.y, iC.w - iC.z, iCR  - iC.w };
#pragma unroll
            for (int j = 0; j < 4; j++) {
                const float gx  = ix[j] * inv_sx;
                const float gy  = iy[j] * inv_sy;
                const float gn2 = gx * gx + gy * gy;
                const float gnI = sqrtf(fmaxf(gn2, EPS_SQRT_C));
                wE[j] = 1.0f / (1.0f + GAMMA_C * gnI * smin);
            }
        }

#pragma unroll
        for (int k = 0; k < KK; k++) {
            const float* pk = pb + (size_t)k * HH * WW;
            const float4 pN  = *(const float4*)(pk + (size_t)hp * WW + w0);
            const float  pNR = has_right ? pk[(size_t)hp * WW + w0 + 4] : pN.w;

            const float pc[4]  = { pC[k].x, pC[k].y, pC[k].z, pC[k].w };
            const float pxp[4] = { pN.x - pC[k].x, pN.y - pC[k].y,
                                   pN.z - pC[k].z, pN.w - pC[k].w };
            const float pyp[4] = { pC[k].y - pC[k].x, pC[k].z - pC[k].y,
                                   pC[k].w - pC[k].z, pCR[k] - pC[k].w };

            float n = 0.0f, d = 0.0f;
#pragma unroll
            for (int j = 0; j < 4; j++) {
                n += pc[j] * (pc[j] + wE[j] * (pxp[j] + pyp[j]));
                d += pc[j] * (1.0f + 2.0f * wE[j]);
            }
            nom[k] += n;
            den[k] += d;

            pC[k]  = pN;
            pCR[k] = pNR;
        }
        iC  = iN;
        iCR = iNR;
    }

    // ---- Block reduction of 16 quantities (nom[0..7], den[0..7]) ----
    __shared__ float sred[8][16];     // [warp][quantity]
    const int lane = threadIdx.x & 31;
    const int warp = threadIdx.x >> 5;

#pragma unroll
    for (int q = 0; q < 16; q++) {
        float v = (q < 8) ? nom[q] : den[q - 8];
#pragma unroll
        for (int off = 16; off > 0; off >>= 1)
            v += __shfl_xor_sync(0xFFFFFFFFu, v, off);
        if (lane == 0) sred[warp][q] = v;
    }
    __syncthreads();

    if (threadIdx.x < 16) {
        const int q = threadIdx.x;
        float v = 0.0f;
#pragma unroll
        for (int wp = 0; wp < 8; wp++) v += sred[wp][q];
        const int idx = (q < 8) ? (b * KK + q)
                                : (BB * KK + b * KK + (q - 8));
        atomicAdd(&g_acc[idx], v);
    }
}

__global__ void finalize_kernel(float* __restrict__ out) {
    __shared__ float s[BB * KK];
    const int i = threadIdx.x;            // 64 threads
    s[i] = g_acc[i] / g_acc[BB * KK + i]; // cut_cost[b,k]
    __syncthreads();
    if (i == 0) {
        float sum = 0.0f;
        for (int j = 0; j < BB * KK; j++) sum += s[j];
        out[0] = (float)(BB * KK) - sum;
    }
}

extern "C" void kernel_launch(void* const* d_in, const int* in_sizes, int n_in,
                              void* d_out, int out_size) {
    const float* img     = (const float*)d_in[0];  // input_images (8,1,1024,1024)
    const float* spacing = (const float*)d_in[1];  // spacing (2,)
    const float* p       = (const float*)d_in[2];  // label_probabilities (8,8,1024,1024)
    float* out = (float*)d_out;

    zero_acc_kernel<<<1, 2 * BB * KK>>>();

    dim3 grid(1, HH / CH, BB);   // (1, 64, 8)
    clustering_main_kernel<<<grid, 256>>>(img, spacing, p);

    finalize_kernel<<<1, BB * KK>>>(out);
}

// round 4
// speedup vs baseline: 1.6379x; 1.6379x over previous
#include <cuda_runtime.h>
#include <cuda_bf16.h>

// Fixed shapes from setup_inputs
#define BB 8
#define KK 8
#define HH 1024
#define WW 1024
#define CH 8                 // rows per block chunk
#define NBY (HH / CH)        // 128 blocks along H
#define GAMMA_C 10.0f
#define EPS_SQRT_C 1e-24f

// Per-block partial sums: [blockIdx.y][b*16 + q]; q<8: nom[k=q], q>=8: den[k=q-8]
// Every slot is written exactly once per run -> no zeroing kernel needed.
__device__ float g_part[NBY * BB * 16];

__global__ __launch_bounds__(256, 2) void clustering_main_kernel(
    const float* __restrict__ img,      // (B,1,H,W)
    const float* __restrict__ spacing,  // (2,)
    const float* __restrict__ p)        // (B,K,H,W)
{
    const int b    = blockIdx.z;
    const int h0   = blockIdx.y * CH;
    const int w0   = 4 * threadIdx.x;        // 256 threads cover W=1024 via float4
    const int lane = threadIdx.x & 31;
    const bool lastcol = (w0 + 4 >= WW);     // only global last thread

    const float sx = spacing[0];
    const float sy = spacing[1];
    const float smin   = fminf(sx, sy);
    const float inv_sx = 1.0f / sx;
    const float inv_sy = 1.0f / sy;

    const float* __restrict__ Ib = img + (size_t)b * HH * WW;
    const float* __restrict__ pb = p   + (size_t)b * KK * HH * WW;

    float nom[KK], den[KK];
#pragma unroll
    for (int k = 0; k < KK; k++) { nom[k] = 0.0f; den[k] = 0.0f; }

    // Prime current row registers (row h0)
    float4 iC = *(const float4*)(Ib + (size_t)h0 * WW + w0);
    float4 pC[KK];
#pragma unroll
    for (int k = 0; k < KK; k++)
        pC[k] = *(const float4*)(pb + (size_t)k * HH * WW + (size_t)h0 * WW + w0);

    for (int r = 0; r < CH; r++) {
        const int h  = h0 + r;
        const int hp = (h + 1 < HH) ? (h + 1) : (HH - 1);

        // ---- issue all next-row loads up front (independent -> batched MLP) ----
        float4 iN = *(const float4*)(Ib + (size_t)hp * WW + w0);
        float4 pN[KK];
#pragma unroll
        for (int k = 0; k < KK; k++)
            pN[k] = *(const float4*)(pb + (size_t)k * HH * WW + (size_t)hp * WW + w0);

        // ---- right-neighbor of current I row via shuffle (lane31: scalar L1 load) ----
        float iR = __shfl_down_sync(0xFFFFFFFFu, iC.x, 1);
        if (lane == 31)
            iR = lastcol ? iC.w : __ldg(Ib + (size_t)h * WW + w0 + 4);

        // ---- edge weights, reused across all K channels ----
        float wE[4];
        {
            const float ix[4] = { iN.x - iC.x, iN.y - iC.y, iN.z - iC.z, iN.w - iC.w };
            const float iy[4] = { iC.y - iC.x, iC.z - iC.y, iC.w - iC.z, iR   - iC.w };
#pragma unroll
            for (int j = 0; j < 4; j++) {
                const float gx  = ix[j] * inv_sx;
                const float gy  = iy[j] * inv_sy;
                const float gn2 = gx * gx + gy * gy;
                const float gnI = sqrtf(fmaxf(gn2, EPS_SQRT_C));
                wE[j] = 1.0f / (1.0f + GAMMA_C * gnI * smin);
            }
        }

#pragma unroll
        for (int k = 0; k < KK; k++) {
            float pR = __shfl_down_sync(0xFFFFFFFFu, pC[k].x, 1);
            if (lane == 31)
                pR = lastcol ? pC[k].w
                             : __ldg(pb + (size_t)k * HH * WW + (size_t)h * WW + w0 + 4);

            const float pc[4]  = { pC[k].x, pC[k].y, pC[k].z, pC[k].w };
            const float pxp[4] = { pN[k].x - pC[k].x, pN[k].y - pC[k].y,
                                   pN[k].z - pC[k].z, pN[k].w - pC[k].w };
            const float pyp[4] = { pC[k].y - pC[k].x, pC[k].z - pC[k].y,
                                   pC[k].w - pC[k].z, pR      - pC[k].w };

            float n = 0.0f, d = 0.0f;
#pragma unroll
            for (int j = 0; j < 4; j++) {
                n += pc[j] * (pc[j] + wE[j] * (pxp[j] + pyp[j]));
                d += pc[j] * (1.0f + 2.0f * wE[j]);
            }
            nom[k] += n;
            den[k] += d;

            pC[k] = pN[k];   // roll row registers
        }
        iC = iN;
    }

    // ---- Block reduction of 16 quantities ----
    __shared__ float sred[8][16];
    const int warp = threadIdx.x >> 5;

#pragma unroll
    for (int q = 0; q < 16; q++) {
        float v = (q < 8) ? nom[q] : den[q - 8];
#pragma unroll
        for (int off = 16; off > 0; off >>= 1)
            v += __shfl_xor_sync(0xFFFFFFFFu, v, off);
        if (lane == 0) sred[warp][q] = v;
    }
    __syncthreads();

    if (threadIdx.x < 16) {
        const int q = threadIdx.x;
        float v = 0.0f;
#pragma unroll
        for (int wp = 0; wp < 8; wp++) v += sred[wp][q];
        g_part[(size_t)blockIdx.y * (BB * 16) + b * 16 + q] = v;
    }
}

__global__ void finalize_kernel(float* __restrict__ out) {
    __shared__ float s[BB * 16];
    __shared__ float c[BB * KK];
    const int t = threadIdx.x;             // 128 threads

    // Coalesced: for each y-row, warp reads 32 consecutive floats
    float v = 0.0f;
#pragma unroll 8
    for (int y = 0; y < NBY; y++)
        v += g_part[(size_t)y * (BB * 16) + t];
    s[t] = v;
    __syncthreads();

    if (t < BB * KK) {
        const int bb = t >> 3, kk = t & 7;
        c[t] = s[bb * 16 + kk] / s[bb * 16 + 8 + kk];   // cut_cost[b,k]
    }
    __syncthreads();

    if (t == 0) {
        float sum = 0.0f;
        for (int j = 0; j < BB * KK; j++) sum += c[j];
        out[0] = (float)(BB * KK) - sum;
    }
}

extern "C" void kernel_launch(void* const* d_in, const int* in_sizes, int n_in,
                              void* d_out, int out_size) {
    const float* img     = (const float*)d_in[0];  // (8,1,1024,1024)
    const float* spacing = (const float*)d_in[1];  // (2,)
    const float* p       = (const float*)d_in[2];  // (8,8,1024,1024)
    float* out = (float*)d_out;

    dim3 grid(1, NBY, BB);   // (1, 128, 8) = 1024 blocks
    clustering_main_kernel<<<grid, 256>>>(img, spacing, p);
    finalize_kernel<<<1, 128>>>(out);
}